// round 17
// baseline (speedup 1.0000x reference)
#include <cuda_runtime.h>
#include <math.h>
#include <stdint.h>

// Problem constants (V=8192, F=256, B=32, L=64)
#define VV     8192
#define FF     256
#define BBATCH 32
#define LLEN   64
#define RR     2016
#define RPAD   2048
#define BM     128
#define BN     128
#define KC     32
#define NW     8           // 256 bits = 8 x u32 words
#define NWF    2           // dense filter words (64 bits)
#define CUTOFF 20.0f       // drop logit deficits > 20 (rel err <= 1.2e-4 worst case)
#define NT     64          // fallback n-tiles
#define PCN    64          // dense pc path: n-cols per CTA
#define PCNT   128
#define NTMAX  128
#define MT     16
#define VMASK  (VV - 1)
#define PREPB  (VV / 8)    // 1024 packing blocks
// LSH: 21 chunks (20 x 12 bits + 1 x 16 bits) -> any v with ham<=20 shares a chunk
#define NCH    21
#define HEADSZ (20 * 4096 + 65536)   // 147456 ints
#define RSTB   144                    // head-reset blocks (147456/1024)

struct Cfg { float w0, W, w0x2, thresh, wfc, delta; int flag, ihhi; };

__device__ Cfg      g_cfg;
__device__ int      g_use_pc = 1;   // reset by k_fin each call
__device__ int      g_ticket = 0;   // reset by k_fin each call
__device__ uint32_t g_Bbits[VV * NW];
__device__ int      g_useq[RPAD];
__device__ int      g_tgt[RPAD];
__device__ float    g_sfeat[VV];
__device__ float    g_pm[RPAD * NTMAX];
__device__ float    g_ps[RPAD * NTMAX];
__device__ float    g_rownll[RPAD];
__device__ int      g_head[HEADSZ];     // LSH bucket heads (reset in prep)
__device__ int      g_next[NCH * VV];   // LSH chains

__device__ __forceinline__ float neg_inf() { return __int_as_float(0xff800000u); }

__device__ __forceinline__ uint32_t smem_u32(const void* p) {
    uint32_t a;
    asm("{ .reg .u64 t; cvta.to.shared.u64 t, %1; cvt.u32.u64 %0, t; }" : "=r"(a) : "l"(p));
    return a;
}
#define MBAR_INIT(mb, cnt) asm volatile("mbarrier.init.shared.b64 [%0], %1;" :: "r"(mb), "r"(cnt) : "memory")
#define MBAR_EXPECT_TX(mb, bytes) asm volatile("mbarrier.arrive.expect_tx.shared.b64 _, [%0], %1;" :: "r"(mb), "r"(bytes) : "memory")
#define MBAR_WAIT(mb, ph) do {                                                  \
    uint32_t _m = (mb), _p = (ph), _d;                                          \
    asm volatile("{\n\t.reg .pred p;\n\t"                                       \
        "mbarrier.try_wait.parity.acquire.cta.shared::cta.b64 p, [%1], %2;\n\t" \
        "selp.b32 %0, 1, 0, p;\n\t}" : "=r"(_d) : "r"(_m), "r"(_p) : "memory"); \
    if (!_d) {                                                                  \
        asm volatile("{\n\t.reg .pred P1;\n\t"                                  \
            "WL_%=:\n\t"                                                        \
            "mbarrier.try_wait.parity.acquire.cta.shared::cta.b64 P1, [%0], %1, 0x989680;\n\t" \
            "@P1 bra.uni WD_%=;\n\t bra.uni WL_%=;\n\t WD_%=:\n\t}"             \
            :: "r"(_m), "r"(_p) : "memory");                                    \
    } } while (0)
#define BULK_G2S(smem_dst, gmem_src, bytes, mb)                                 \
    asm volatile("cp.async.bulk.shared::cta.global.mbarrier::complete_tx::bytes " \
        "[%0], [%1], %2, [%3];"                                                 \
        :: "r"(smem_dst), "l"(gmem_src), "r"(bytes), "r"(mb) : "memory")

__device__ __forceinline__ uint32_t nib_of(int4 x) {
    return (uint32_t)(x.x != 0) | ((uint32_t)(x.y != 0) << 1)
         | ((uint32_t)(x.z != 0) << 2) | ((uint32_t)(x.w != 0) << 3);
}
__device__ __forceinline__ int bin_ok(int4 x) {
    return ((x.x | x.y | x.z | x.w) & ~1) == 0 &&
           x.x >= 0 && x.y >= 0 && x.z >= 0 && x.w >= 0;
}
// dynamic word select without local-memory spill
__device__ __forceinline__ uint32_t getw(const uint32_t* w, int i) {
    uint32_t r = 0;
    #pragma unroll
    for (int k = 0; k < 8; k++) r = (k == i) ? w[k] : r;
    return r;
}
// chunk key: chunks 0..19 are 12 bits at bitpos 12c; chunk 20 is 16 bits at 240
__device__ __forceinline__ uint32_t chunk_key(const uint32_t* w, int c) {
    int bitpos = 12 * c;
    int wi = bitpos >> 5, off = bitpos & 31;
    uint32_t lo = getw(w, wi);
    uint32_t hi = (wi < 7) ? getw(w, wi + 1) : 0u;
    uint32_t mask = (c == 20) ? 0xFFFFu : 0xFFFu;
    return (uint32_t)(((((uint64_t)hi << 32) | lo) >> off) & mask);
}
__device__ __forceinline__ int head_off(int c) { return (c < 20) ? c * 4096 : 81920; }

// ---------------------------------------------------------------------------
// PREP: grid = PREPB + 1 + RSTB blocks, 256 threads.
// [0,PREPB): pack 8 rows (8 KB bulk copy); PREPB: cfg+seq; rest: reset heads.
// ---------------------------------------------------------------------------
__global__ void k_prep(const int* __restrict__ feat, const float* __restrict__ w,
                       const int* __restrict__ seq32) {
    const int bid = blockIdx.x, tid = threadIdx.x;

    if (bid < PREPB) {
        __shared__ __align__(16) int sbuf[8 * FF];
        __shared__ __align__(8) unsigned long long s_mbar;

        const uint32_t mb = smem_u32(&s_mbar);
        if (tid == 0) {
            MBAR_INIT(mb, 1);
            asm volatile("fence.proxy.async.shared::cta;" ::: "memory");
            MBAR_EXPECT_TX(mb, 8 * FF * 4);
            BULK_G2S(smem_u32(sbuf), &feat[(size_t)bid * 8 * FF], 8 * FF * 4, mb);
        }
        __syncthreads();
        MBAR_WAIT(mb, 0);

        const int grp = tid >> 6;
        const int t   = tid & 63;
        const int v0  = bid * 8 + grp;

        int4 x0 = *(const int4*)&sbuf[(grp    ) * FF + t * 4];
        int4 x1 = *(const int4*)&sbuf[(grp + 4) * FF + t * 4];
        float wx = w[1 + t * 4 + 0], wy = w[1 + t * 4 + 1];
        float wz = w[1 + t * 4 + 2], ww = w[1 + t * 4 + 3];

        uint32_t n0 = nib_of(x0) << ((t & 7) * 4);
        uint32_t n1 = nib_of(x1) << ((t & 7) * 4);
        #pragma unroll
        for (int o = 1; o < 8; o <<= 1) {
            n0 |= __shfl_xor_sync(0xffffffffu, n0, o);
            n1 |= __shfl_xor_sync(0xffffffffu, n1, o);
        }
        if ((t & 7) == 0) {
            g_Bbits[(v0    ) * NW + (t >> 3)] = n0;
            g_Bbits[(v0 + 4) * NW + (t >> 3)] = n1;
        }

        int ok = bin_ok(x0) && bin_ok(x1);
        if (!__syncthreads_and(ok)) {
            if (tid == 0) atomicAnd(&g_use_pc, 0);
        }

        float p0 = wx * (float)x0.x + wy * (float)x0.y + wz * (float)x0.z + ww * (float)x0.w;
        float p1 = wx * (float)x1.x + wy * (float)x1.y + wz * (float)x1.z + ww * (float)x1.w;
        #pragma unroll
        for (int o = 16; o; o >>= 1) {
            p0 += __shfl_down_sync(0xffffffffu, p0, o);
            p1 += __shfl_down_sync(0xffffffffu, p1, o);
        }
        __shared__ float sred[8][2];
        if ((t & 31) == 0) {
            sred[grp    ][t >> 5] = p0;
            sred[grp + 4][t >> 5] = p1;
        }
        __syncthreads();
        if (tid < 8) g_sfeat[bid * 8 + tid] = sred[tid][0] + sred[tid][1];
        return;
    }

    if (bid > PREPB) {
        // head reset: -1 everywhere
        int base = (bid - PREPB - 1) * 1024 + tid * 4;
        *(int4*)&g_head[base] = make_int4(-1, -1, -1, -1);
        return;
    }

    // ------- tail block: scalar config + sequence decode -------
    {
        float wf = w[1 + tid];
        float s = wf, mn = wf, mx = wf;
        #pragma unroll
        for (int o = 16; o; o >>= 1) {
            s  += __shfl_down_sync(0xffffffffu, s, o);
            mn  = fminf(mn, __shfl_down_sync(0xffffffffu, mn, o));
            mx  = fmaxf(mx, __shfl_down_sync(0xffffffffu, mx, o));
        }
        __shared__ float ssum[8], smin[8], smax[8];
        __shared__ int s_st;
        if ((tid & 31) == 0) { ssum[tid >> 5] = s; smin[tid >> 5] = mn; smax[tid >> 5] = mx; }
        if (tid < 32) {
            int odd = seq32[2 * tid + 1];
            uint32_t nz = __ballot_sync(0xffffffffu, odd != 0);
            if (tid == 0) s_st = (nz == 0) ? 2 : 1;
        }
        __syncthreads();
        if (tid == 0) {
            float S = 0.f, MN = 3.0e38f, MX = -3.0e38f;
            #pragma unroll
            for (int i = 0; i < 8; i++) {
                S += ssum[i]; MN = fminf(MN, smin[i]); MX = fmaxf(MX, smax[i]);
            }
            float w0 = w[0];
            Cfg c;
            c.w0 = w0; c.W = S; c.w0x2 = 2.0f * w0;
            c.flag = (w0 >= 0.f && MN >= 0.f) ? 1 : 0;
            c.thresh = w0 * S - 33.0f;
            c.wfc = MN;
            c.delta = w0 * MN;
            if (c.delta > 0.f) {
                float hf = CUTOFF / c.delta;
                c.ihhi = (hf >= 256.f) ? 256 : (int)hf;
            } else {
                c.ihhi = 256;
            }
            g_cfg = c;
            atomicAnd(&g_use_pc, (MN == MX && c.flag) ? 1 : 0);
        }
        const int st = s_st;
        #pragma unroll
        for (int it = 0; it < 8; it++) {
            int r = it * 256 + tid;
            if (r < RR) {
                int b = r / (LLEN - 1), t2 = r % (LLEN - 1);
                g_useq[r] = seq32[(b * LLEN + t2) * st] & VMASK;
                g_tgt[r]  = seq32[(b * LLEN + t2 + 1) * st] & VMASK;
            } else {
                g_useq[r] = 0; g_tgt[r] = 0;
            }
        }
    }
}

// ---------------------------------------------------------------------------
// BUILD: insert all 8192 vocab rows into 21 chunk tables. grid 32 x 256.
// ---------------------------------------------------------------------------
__global__ void k_build() {
    if (!(g_use_pc && g_cfg.ihhi <= 20)) return;
    int v = blockIdx.x * 256 + threadIdx.x;
    uint4 a = *(const uint4*)&g_Bbits[(size_t)v * NW];
    uint4 b = *(const uint4*)&g_Bbits[(size_t)v * NW + 4];
    uint32_t wv[8] = {a.x, a.y, a.z, a.w, b.x, b.y, b.z, b.w};
    #pragma unroll
    for (int c = 0; c < NCH; c++) {
        uint32_t key = chunk_key(wv, c);   // compile-time wi after unroll
        g_next[c * VV + v] = atomicExch(&g_head[head_off(c) + key], v);
    }
}

// ---------------------------------------------------------------------------
// MAIN: dense paths only. LSH mode (use_pc && ihhi<=20) exits immediately.
// ---------------------------------------------------------------------------
__global__ __launch_bounds__(256, 4) void k_main(const int* __restrict__ feat,
                                                 const float* __restrict__ w) {
    __shared__ __align__(16) char U[32768];
    const int tid = threadIdx.x;
    const Cfg c = g_cfg;

    if (g_use_pc) {
        if (c.ihhi <= 20) return;   // LSH path handles it in k_fin
        uint32_t (*sA)[NW] = (uint32_t(*)[NW])(U);
        uint32_t (*sB)[NW] = (uint32_t(*)[NW])(U + 4096);
        float* tbl         = (float*)(U + 6144);

        const int tx = tid & 7, ty = tid >> 3;
        const int n0 = blockIdx.x * PCN, m0 = blockIdx.y * BM;
        const float delta = c.delta;
        const int   ihhi  = c.ihhi;

        tbl[tid] = __expf(-delta * (float)tid);
        if (tid == 0) tbl[256] = __expf(-delta * 256.f);

        {
            int r = tid >> 1, h = (tid & 1) << 2;
            int sw = (r >> 2) & 7;
            int u = g_useq[m0 + r];
            uint4 a = *(const uint4*)&g_Bbits[(size_t)u * NW + h];
            sA[r][(h + 0) ^ sw] = a.x; sA[r][(h + 1) ^ sw] = a.y;
            sA[r][(h + 2) ^ sw] = a.z; sA[r][(h + 3) ^ sw] = a.w;
        }
        if (tid < 128) {
            int r = tid >> 1, h = (tid & 1) << 2;
            int sw = (r >> 3) & 7;
            uint4 b = *(const uint4*)&g_Bbits[(size_t)(n0 + r) * NW + h];
            sB[r][(h + 0) ^ sw] = b.x; sB[r][(h + 1) ^ sw] = b.y;
            sB[r][(h + 2) ^ sw] = b.z; sB[r][(h + 3) ^ sw] = b.w;
        }
        __syncthreads();

        int acc[4][8];
        #pragma unroll
        for (int i = 0; i < 4; i++)
            #pragma unroll
            for (int j = 0; j < 8; j++) acc[i][j] = 0;

        const int swa = ty & 7;
        #pragma unroll
        for (int wi = 0; wi < NWF; wi++) {
            uint32_t av[4], bv[8];
            #pragma unroll
            for (int i = 0; i < 4; i++) av[i] = sA[ty * 4 + i][wi ^ swa];
            #pragma unroll
            for (int j = 0; j < 8; j++) bv[j] = sB[tx * 8 + j][wi ^ tx];
            #pragma unroll
            for (int i = 0; i < 4; i++)
                #pragma unroll
                for (int j = 0; j < 8; j++)
                    acc[i][j] += __popc(av[i] ^ bv[j]);
        }

        int hmin = acc[0][0];
        #pragma unroll
        for (int i = 0; i < 4; i++)
            #pragma unroll
            for (int j = 0; j < 8; j++) hmin = min(hmin, acc[i][j]);

        float s[4] = {0.f, 0.f, 0.f, 0.f};
        if (hmin <= ihhi) {
            #pragma unroll
            for (int i = 0; i < 4; i++) {
                #pragma unroll
                for (int j = 0; j < 8; j++) {
                    if (acc[i][j] <= ihhi) {
                        int h = acc[i][j];
                        #pragma unroll
                        for (int wi = NWF; wi < 8; wi++)
                            h += __popc(sA[ty * 4 + i][wi ^ swa] ^ sB[tx * 8 + j][wi ^ tx]);
                        s[i] += tbl[h];
                    }
                }
            }
        }
        #pragma unroll
        for (int i = 0; i < 4; i++) {
            #pragma unroll
            for (int o = 1; o < 8; o <<= 1)
                s[i] += __shfl_xor_sync(0xffffffffu, s[i], o);
        }
        if (tx == 0) {
            #pragma unroll
            for (int i = 0; i < 4; i++)
                g_ps[(size_t)(m0 + ty * 4 + i) * NTMAX + blockIdx.x] = s[i];
        }
        return;
    }

    // ---------------- fallback fp32 GEMM ----------------
    if (blockIdx.x >= NT) return;
    float (*As)[BM] = (float(*)[BM])(U);
    float (*Bs)[BN] = (float(*)[BN])(U + 16384);

    const int tx = tid & 15, ty = tid >> 4;
    const int m0 = blockIdx.y * BM, n0 = blockIdx.x * BN;
    const int ldrow = tid >> 3;
    const int ldc   = (tid & 7) << 2;

    float acc[8][8];
    #pragma unroll
    for (int i = 0; i < 8; i++)
        #pragma unroll
        for (int j = 0; j < 8; j++) acc[i][j] = 0.f;

    for (int k0 = 0; k0 < FF; k0 += KC) {
        float w0c = w[1 + k0 + ldc + 0], w1c = w[1 + k0 + ldc + 1];
        float w2c = w[1 + k0 + ldc + 2], w3c = w[1 + k0 + ldc + 3];
        #pragma unroll
        for (int q = 0; q < 4; q++) {
            int row = ldrow + q * 32;
            int ua = g_useq[m0 + row];
            int4 a = *(const int4*)&feat[(size_t)ua * FF + k0 + ldc];
            As[ldc + 0][row] = w0c * (float)a.x; As[ldc + 1][row] = w1c * (float)a.y;
            As[ldc + 2][row] = w2c * (float)a.z; As[ldc + 3][row] = w3c * (float)a.w;
            int4 b = *(const int4*)&feat[(size_t)(n0 + row) * FF + k0 + ldc];
            Bs[ldc + 0][row] = (float)b.x; Bs[ldc + 1][row] = (float)b.y;
            Bs[ldc + 2][row] = (float)b.z; Bs[ldc + 3][row] = (float)b.w;
        }
        __syncthreads();
        #pragma unroll
        for (int k = 0; k < KC; k++) {
            float4 a0 = *(const float4*)&As[k][ty * 8];
            float4 a1 = *(const float4*)&As[k][ty * 8 + 4];
            float4 b0 = *(const float4*)&Bs[k][tx * 8];
            float4 b1 = *(const float4*)&Bs[k][tx * 8 + 4];
            float av[8] = {a0.x, a0.y, a0.z, a0.w, a1.x, a1.y, a1.z, a1.w};
            float bv[8] = {b0.x, b0.y, b0.z, b0.w, b1.x, b1.y, b1.z, b1.w};
            #pragma unroll
            for (int i = 0; i < 8; i++)
                #pragma unroll
                for (int j = 0; j < 8; j++)
                    acc[i][j] = fmaf(av[i], bv[j], acc[i][j]);
        }
        __syncthreads();
    }

    float (*red_m)[16] = (float(*)[16])(U);
    float (*red_s)[16] = (float(*)[16])(U + 8192);

    float sv[8];
    #pragma unroll
    for (int j = 0; j < 8; j++) sv[j] = g_sfeat[n0 + tx * 8 + j];

    #pragma unroll
    for (int i = 0; i < 8; i++) {
        int m = ty * 8 + i;
        int uu = g_useq[m0 + m];
        float rb = c.w0 * (c.W - g_sfeat[uu]);
        float mi = neg_inf(), si = 0.f;
        #pragma unroll
        for (int j = 0; j < 8; j++) {
            float x = c.w0x2 * acc[i][j] - c.w0 * sv[j] + rb;
            if (!c.flag || x > c.thresh) {
                if (x > mi) { si = si * __expf(mi - x) + 1.0f; mi = x; }
                else        { si += __expf(x - mi); }
            }
        }
        red_m[m][tx] = mi;
        red_s[m][tx] = si;
    }
    __syncthreads();

    if (tid < BM) {
        float mm = neg_inf(), ss = 0.f;
        #pragma unroll
        for (int k = 0; k < 16; k++) {
            float mk = red_m[tid][k], sk = red_s[tid][k];
            if (sk > 0.f) {
                if (mk > mm) { ss = ss * __expf(mm - mk) + sk; mm = mk; }
                else         { ss += sk * __expf(mk - mm); }
            }
        }
        g_pm[(size_t)(m0 + tid) * NTMAX + blockIdx.x] = mm;
        g_ps[(size_t)(m0 + tid) * NTMAX + blockIdx.x] = ss;
    }
}

// ---------------------------------------------------------------------------
// FIN: grid 63 x 1024 (one warp per row). Three modes: LSH / dense-pc / f32.
// Last block reduces all row NLLs deterministically and resets globals.
// ---------------------------------------------------------------------------
__global__ void k_fin(const int* __restrict__ feat, const float* __restrict__ w,
                      float* __restrict__ out) {
    __shared__ int s_last;
    int tid = threadIdx.x, lane = tid & 31, wid = tid >> 5;
    int r = blockIdx.x * 32 + wid;
    const int use_pc = g_use_pc;
    const Cfg c = g_cfg;
    const int use_lsh = use_pc && (c.ihhi <= 20);

    {
        float lse, xt;
        int tg = g_tgt[r];
        int u = g_useq[r];
        if (use_lsh) {
            // gather u's 8 words to all lanes
            uint32_t uw[8];
            {
                uint32_t myw = (lane < NW) ? g_Bbits[(size_t)u * NW + lane] : 0u;
                #pragma unroll
                for (int i = 0; i < 8; i++)
                    uw[i] = __shfl_sync(0xffffffffu, myw, i);
            }
            float s = 0.f;
            if (lane < NCH) {
                const int ch = lane;
                uint32_t ukey = chunk_key(uw, ch);
                int v = g_head[head_off(ch) + ukey];
                while (v >= 0) {
                    uint4 a = *(const uint4*)&g_Bbits[(size_t)v * NW];
                    uint4 b = *(const uint4*)&g_Bbits[(size_t)v * NW + 4];
                    uint32_t vw[8] = {a.x, a.y, a.z, a.w, b.x, b.y, b.z, b.w};
                    // dedup: count only if no earlier chunk matches
                    int dup = 0;
                    #pragma unroll
                    for (int cc = 0; cc < 20; cc++) {
                        if (cc < ch) {
                            int w2 = (cc * 12) >> 5, o2 = (cc * 12) & 31;
                            uint32_t ul = uw[w2], vl = vw[w2];
                            uint32_t uh = (w2 < 7) ? uw[w2 + 1] : 0u;
                            uint32_t vh = (w2 < 7) ? vw[w2 + 1] : 0u;
                            uint32_t ku = (uint32_t)(((((uint64_t)uh << 32) | ul) >> o2) & 0xFFFu);
                            uint32_t kv = (uint32_t)(((((uint64_t)vh << 32) | vl) >> o2) & 0xFFFu);
                            if (ku == kv) dup = 1;
                        }
                    }
                    if (!dup) {
                        int h = 0;
                        #pragma unroll
                        for (int k2 = 0; k2 < 8; k2++) h += __popc(uw[k2] ^ vw[k2]);
                        s += __expf(-c.delta * (float)h);
                    }
                    v = g_next[ch * VV + v];
                }
            }
            #pragma unroll
            for (int o = 16; o; o >>= 1) s += __shfl_down_sync(0xffffffffu, s, o);
            lse = c.delta * 256.f + logf(s);
            int h = (lane < NW)
                  ? __popc(uw[lane] ^ g_Bbits[(size_t)tg * NW + lane]) : 0;
            #pragma unroll
            for (int o = 16; o; o >>= 1) h += __shfl_down_sync(0xffffffffu, h, o);
            xt = c.delta * (256.f - (float)h);
        } else if (use_pc) {
            float s = 0.f;
            #pragma unroll
            for (int q = 0; q < 4; q++) s += g_ps[(size_t)r * NTMAX + lane + 32 * q];
            #pragma unroll
            for (int o = 16; o; o >>= 1) s += __shfl_down_sync(0xffffffffu, s, o);
            lse = c.delta * 256.f + logf(s);
            int h = (lane < NW)
                  ? __popc(g_Bbits[u * NW + lane] ^ g_Bbits[tg * NW + lane]) : 0;
            #pragma unroll
            for (int o = 16; o; o >>= 1) h += __shfl_down_sync(0xffffffffu, h, o);
            xt = c.delta * (256.f - (float)h);
        } else {
            float mm = neg_inf(), ss = 0.f;
            #pragma unroll
            for (int q = 0; q < 2; q++) {
                int k = lane + 32 * q;
                float mk = g_pm[(size_t)r * NTMAX + k], sk = g_ps[(size_t)r * NTMAX + k];
                if (sk > 0.f) {
                    if (mk > mm) { ss = ss * __expf(mm - mk) + sk; mm = mk; }
                    else         { ss += sk * __expf(mk - mm); }
                }
            }
            #pragma unroll
            for (int o = 16; o; o >>= 1) {
                float mo = __shfl_down_sync(0xffffffffu, mm, o);
                float so = __shfl_down_sync(0xffffffffu, ss, o);
                if (so > 0.f) {
                    if (mo > mm) { ss = ss * __expf(mm - mo) + so; mm = mo; }
                    else         { ss += so * __expf(mo - mm); }
                }
            }
            lse = mm + logf(ss);
            float dot = 0.f;
            #pragma unroll
            for (int q = 0; q < 2; q++) {
                int f0 = q * 128 + lane * 4;
                int4 a = *(const int4*)&feat[(size_t)u  * FF + f0];
                int4 b = *(const int4*)&feat[(size_t)tg * FF + f0];
                dot += w[1 + f0 + 0] * (float)(a.x * b.x) + w[1 + f0 + 1] * (float)(a.y * b.y)
                     + w[1 + f0 + 2] * (float)(a.z * b.z) + w[1 + f0 + 3] * (float)(a.w * b.w);
            }
            #pragma unroll
            for (int o = 16; o; o >>= 1) dot += __shfl_down_sync(0xffffffffu, dot, o);
            float rb = c.w0 * (c.W - g_sfeat[u]);
            xt = c.w0x2 * dot - c.w0 * g_sfeat[tg] + rb;
        }
        if (lane == 0) g_rownll[r] = lse - xt;
    }

    __syncthreads();
    if (tid == 0) {
        __threadfence();
        int t = atomicAdd(&g_ticket, 1);
        s_last = (t == gridDim.x - 1);
    }
    __syncthreads();
    if (s_last) {
        __threadfence();
        __shared__ float red[1024];
        float v = 0.f;
        if (tid < RR)        v += g_rownll[tid];
        if (tid + 1024 < RR) v += g_rownll[tid + 1024];
        red[tid] = v;
        __syncthreads();
        #pragma unroll
        for (int s = 512; s > 0; s >>= 1) {
            if (tid < s) red[tid] += red[tid + s];
            __syncthreads();
        }
        if (tid == 0) {
            out[0] = red[0] + (float)BBATCH * logf((float)VV);
            g_ticket = 0;     // reset for next graph replay
            g_use_pc = 1;
        }
    }
}

// ---------------------------------------------------------------------------
extern "C" void kernel_launch(void* const* d_in, const int* in_sizes, int n_in,
                              void* d_out, int out_size) {
    const float* w    = 0;
    const int*   feat = 0;
    const int*   seq  = 0;
    for (int i = 0; i < n_in; i++) {
        if      (in_sizes[i] == FF + 1)        w    = (const float*)d_in[i];
        else if (in_sizes[i] == VV * FF)       feat = (const int*)d_in[i];
        else if (in_sizes[i] == BBATCH * LLEN) seq  = (const int*)d_in[i];
    }
    if (!w || !feat || !seq) {
        w    = (const float*)d_in[0];
        feat = (const int*)d_in[1];
        seq  = (const int*)d_in[2];
    }

    k_prep<<<PREPB + 1 + RSTB, 256>>>(feat, w, seq);
    k_build<<<32, 256>>>();
    k_main<<<dim3(PCNT, MT), 256>>>(feat, w);
    k_fin<<<63, 1024>>>(feat, w, (float*)d_out);
}